// round 13
// baseline (speedup 1.0000x reference)
#include <cuda_runtime.h>
#include <cuda_fp16.h>
#include <math.h>
#include <stdint.h>

// Problem constants
#define B_    16
#define CIN   512
#define COUT  512
#define HW    1024          // 32*32
#define NTOT  16384         // B_*HW
#define MTOT  4608          // 9*COUT
#define OH    64
#define OHW   4096          // 64*64

// GEMM tiling
#define BM 128
#define BN 128
#define BKE 32              // k elements per stage chunk
#define KSTEPS (CIN / BKE)  // 16
#define TILE_B (128 * 80)   // one 128x32 fp16 tile @ 80B row stride (10240B)

// ---- device scratch (no allocations allowed) ----
__device__ float g_style[B_ * CIN];
__device__ float g_dcoef[B_ * COUT];
__device__ float g_wsq[CIN * COUT];
__device__ __align__(256) __half g_A[(size_t)MTOT * CIN];   // [m][k] fp16
__device__ __align__(256) __half g_B[(size_t)NTOT * CIN];   // [n][k] fp16
__device__ __align__(256) float g_C[(size_t)MTOT * NTOT];   // ~302MB

// ---------------- helpers ----------------
__device__ __forceinline__ uint32_t smem_u32(const void* p) {
    uint32_t a;
    asm("{ .reg .u64 t; cvta.to.shared.u64 t, %1; cvt.u32.u64 %0, t; }" : "=r"(a) : "l"(p));
    return a;
}

#define LDSM_X4(r, addr) \
    asm volatile("ldmatrix.sync.aligned.m8n8.x4.shared.b16 {%0,%1,%2,%3}, [%4];" \
        : "=r"((r)[0]), "=r"((r)[1]), "=r"((r)[2]), "=r"((r)[3]) : "r"(addr))

#define MMA16816F16(c, a, b0v, b1v) \
    asm volatile("mma.sync.aligned.m16n8k16.row.col.f32.f16.f16.f32 " \
        "{%0,%1,%2,%3},{%4,%5,%6,%7},{%8,%9},{%0,%1,%2,%3};" \
        : "+f"((c)[0]), "+f"((c)[1]), "+f"((c)[2]), "+f"((c)[3]) \
        : "r"((a)[0]), "r"((a)[1]), "r"((a)[2]), "r"((a)[3]), "r"(b0v), "r"(b1v))

// FIR/phase mixing coefficients (see derivation in R1)
__device__ __forceinline__ float AA(int phi, int o, int ki) {
    const float tab[2][3][3] = {
        {{0.25f, 0.00f, 0.00f},
         {0.75f, 0.75f, 0.25f},
         {0.00f, 0.25f, 0.75f}},
        {{0.75f, 0.25f, 0.00f},
         {0.25f, 0.75f, 0.75f},
         {0.00f, 0.00f, 0.25f}}
    };
    return tab[phi][o][ki];
}

// ---------------------------------------------------------------------------
// 1) style[b,ci]
__global__ void style_kernel(const float* __restrict__ wl,
                             const float* __restrict__ aw,
                             const float* __restrict__ ab) {
    int b = blockIdx.x;
    __shared__ float sw[CIN];
    for (int i = threadIdx.x; i < CIN; i += blockDim.x) sw[i] = wl[b * CIN + i];
    __syncthreads();
    int warp = threadIdx.x >> 5, lane = threadIdx.x & 31;
    for (int ci = warp; ci < CIN; ci += 16) {
        float acc = 0.f;
        const float* row = aw + (size_t)ci * CIN;
        #pragma unroll 4
        for (int d = lane; d < CIN; d += 32) acc += sw[d] * row[d];
        #pragma unroll
        for (int off = 16; off; off >>= 1) acc += __shfl_xor_sync(0xffffffffu, acc, off);
        if (lane == 0)
            g_style[b * CIN + ci] = acc * 0.04419417382415922f + ab[ci];
    }
}

// ---------------------------------------------------------------------------
// 2) weights: wsq + fp16 A [m][k]
__global__ void prep_w_kernel(const float* __restrict__ cw) {
    int co = blockIdx.x;
    int ci = threadIdx.x;
    const float* wp = cw + ((size_t)co * CIN + ci) * 9;
    float w[9];
    float q = 0.f;
    #pragma unroll
    for (int t = 0; t < 9; t++) { w[t] = wp[t]; q += w[t] * w[t]; }
    g_wsq[ci * COUT + co] = q;
    #pragma unroll
    for (int t = 0; t < 9; t++)
        g_A[(size_t)(t * COUT + co) * CIN + ci] = __float2half(w[t]);
}

// ---------------------------------------------------------------------------
// 3) dcoef (launched AFTER gemm; only fuse depends on it)
__global__ void dcoef_kernel() {
    int b = blockIdx.x;
    int co = threadIdx.x;
    __shared__ float s2[CIN];
    for (int i = threadIdx.x; i < CIN; i += blockDim.x) {
        float s = g_style[b * CIN + i];
        s2[i] = s * s;
    }
    __syncthreads();
    float acc = 0.f;
    #pragma unroll 4
    for (int ci = 0; ci < CIN; ci++) acc += s2[ci] * g_wsq[ci * COUT + co];
    g_dcoef[b * COUT + co] = rsqrtf(acc + 1e-8f);
}

// ---------------------------------------------------------------------------
// 4) modulate + transpose: B[n][k] fp16
__global__ void modx_t_kernel(const float* __restrict__ x) {
    __shared__ float tile[32][33];
    int ci0 = blockIdx.x * 32, hw0 = blockIdx.y * 32, b = blockIdx.z;
    int tx = threadIdx.x, ty = threadIdx.y;
    #pragma unroll
    for (int r = 0; r < 4; r++) {
        int ci = ci0 + ty + r * 8;
        float s = g_style[b * CIN + ci];
        tile[ty + r * 8][tx] = x[((size_t)b * CIN + ci) * HW + hw0 + tx] * s;
    }
    __syncthreads();
    #pragma unroll
    for (int r = 0; r < 4; r++) {
        int hw = hw0 + ty + r * 8;
        g_B[(size_t)(b * HW + hw) * CIN + ci0 + tx] = __float2half(tile[tx][ty + r * 8]);
    }
}

// ---------------------------------------------------------------------------
// 5) GEMM via mma.sync fp16: C = A * B^T
__global__ __launch_bounds__(256, 2) void gemm_mma_kernel() {
    __shared__ __align__(128) char dsm[2][2 * TILE_B];   // [stage][A|B]

    int tid = threadIdx.x, wid = tid >> 5, lane = tid & 31;
    int m0 = blockIdx.y * BM, n0 = blockIdx.x * BN;
    int wm = wid & 1, wn = wid >> 1;   // 2 (M) x 4 (N) warps

    float acc[4][4][4];
    #pragma unroll
    for (int i = 0; i < 4; i++)
        #pragma unroll
        for (int j = 0; j < 4; j++)
            #pragma unroll
            for (int q = 0; q < 4; q++) acc[i][j][q] = 0.f;

    auto load_stage = [&](int stg, int ks) {
        uint32_t base = smem_u32(&dsm[stg][0]);
        int k0 = ks * BKE;
        #pragma unroll
        for (int i = 0; i < 4; i++) {
            int u = tid + 256 * i;          // 0..1023
            int t2 = u >> 9;                 // 0: A, 1: B
            int v = u & 511;
            int r = v >> 2, c = v & 3;
            const __half* src = (t2 == 0)
                ? g_A + (size_t)(m0 + r) * CIN + k0 + c * 8
                : g_B + (size_t)(n0 + r) * CIN + k0 + c * 8;
            uint32_t dst = base + t2 * TILE_B + r * 80 + c * 16;
            asm volatile("cp.async.cg.shared.global [%0], [%1], 16;" :: "r"(dst), "l"(src) : "memory");
        }
        asm volatile("cp.async.commit_group;" ::: "memory");
    };

    load_stage(0, 0);

    for (int s = 0; s < KSTEPS; s++) {
        asm volatile("cp.async.wait_group 0;" ::: "memory");
        __syncthreads();
        if (s + 1 < KSTEPS) load_stage((s + 1) & 1, s + 1);

        uint32_t base = smem_u32(&dsm[s & 1][0]);
        uint32_t aBs = base;
        uint32_t bBs = base + TILE_B;

        #pragma unroll
        for (int kh = 0; kh < 2; kh++) {
            uint32_t koff = kh * 32 + (lane >> 4) * 16;
            uint32_t a[4][4], bfr[2][4];
            #pragma unroll
            for (int mf = 0; mf < 4; mf++) {
                int row = wm * 64 + mf * 16 + (lane & 15);
                LDSM_X4(a[mf], aBs + row * 80 + koff);
            }
            #pragma unroll
            for (int ng = 0; ng < 2; ng++) {
                int row = wn * 32 + ng * 16 + (lane & 15);
                LDSM_X4(bfr[ng], bBs + row * 80 + koff);
            }
            #pragma unroll
            for (int mf = 0; mf < 4; mf++)
                #pragma unroll
                for (int nf = 0; nf < 4; nf++) {
                    uint32_t b0v = bfr[nf >> 1][nf & 1];
                    uint32_t b1v = bfr[nf >> 1][(nf & 1) + 2];
                    MMA16816F16(acc[mf][nf], a[mf], b0v, b1v);
                }
        }
    }

    // epilogue: write C
    #pragma unroll
    for (int mf = 0; mf < 4; mf++) {
        int mrow = m0 + wm * 64 + mf * 16 + (lane >> 2);
        #pragma unroll
        for (int nf = 0; nf < 4; nf++) {
            int ncol = n0 + wn * 32 + nf * 8 + (lane & 3) * 2;
            *(float2*)(g_C + (size_t)mrow * NTOT + ncol) =
                make_float2(acc[mf][nf][0], acc[mf][nf][1]);
            *(float2*)(g_C + (size_t)(mrow + 8) * NTOT + ncol) =
                make_float2(acc[mf][nf][2], acc[mf][nf][3]);
        }
    }
}

// ---------------------------------------------------------------------------
// 6) fuse: FIR assembly + dcoef + noise + bias + lrelu + clamp
// Cs layout: [9][34][40], interior at rows 1..32, cols 4..35 (16B-aligned)
#define CSROW 40
__global__ __launch_bounds__(256) void fuse_kernel(const float* __restrict__ noise,
                                                   const float* __restrict__ ns_p,
                                                   const float* __restrict__ bias,
                                                   float* __restrict__ out) {
    int co = blockIdx.x, b = blockIdx.y;
    __shared__ float Cs[9][34][CSROW];   // 49 KB

    // zero-fill (vectorized)
    float4* csv = (float4*)&Cs[0][0][0];
    #pragma unroll
    for (int i = 0; i < 12; i++) {
        int idx = threadIdx.x + 256 * i;          // 0..3071, need 3060
        if (idx < 9 * 34 * CSROW / 4) csv[idx] = make_float4(0.f, 0.f, 0.f, 0.f);
    }
    __syncthreads();

    // interior load: per tap, each thread loads one float4 (aligned both sides)
    {
        int v = threadIdx.x * 4;
        int i = v >> 5, j = v & 31;
        const size_t cbase = (size_t)b * HW + i * 32 + j;
        #pragma unroll
        for (int t = 0; t < 9; t++) {
            float4 val = *(const float4*)(g_C + (size_t)(t * COUT + co) * NTOT + cbase);
            *(float4*)&Cs[t][1 + i][4 + j] = val;
        }
    }
    __syncthreads();

    int bi = threadIdx.x >> 4, bj = threadIdx.x & 15;
    float acc[4][4] = {};

    #pragma unroll
    for (int t = 0; t < 9; t++) {
        int ki = t / 3, kj = t % 3;
        float c[4][4];
        #pragma unroll
        for (int r = 0; r < 4; r++)
            #pragma unroll
            for (int cc = 0; cc < 4; cc++)
                c[r][cc] = Cs[t][2 * bi + r][3 + 2 * bj + cc];  // (input col -1) -> 4 + (2bj-1+cc)
        #pragma unroll
        for (int pi = 0; pi < 4; pi++) {
            int di = pi >> 1, phi = pi & 1;
            #pragma unroll
            for (int pj = 0; pj < 4; pj++) {
                int dj = pj >> 1, psi = pj & 1;
                #pragma unroll
                for (int oi = 0; oi < 3; oi++) {
                    float ai = AA(phi, oi, ki);
                    if (ai == 0.f) continue;
                    #pragma unroll
                    for (int oj = 0; oj < 3; oj++) {
                        float aj = AA(psi, oj, kj);
                        if (aj == 0.f) continue;
                        acc[pi][pj] += (ai * aj) * c[di + 2 - oi][dj + 2 - oj];
                    }
                }
            }
        }
    }

    float dval = g_dcoef[b * COUT + co];
    float ns = ns_p[0];
    float bv = bias[co];
    const float* np = noise + (size_t)b * OHW;
    float* op = out + ((size_t)b * COUT + co) * OHW;

    #pragma unroll
    for (int pi = 0; pi < 4; pi++) {
        int P = 4 * bi + pi;
        #pragma unroll
        for (int pj = 0; pj < 4; pj++) {
            int Q = 4 * bj + pj;
            float v = acc[pi][pj] * dval + np[P * OH + Q] * ns + bv;
            v = (v > 0.f) ? v : 0.2f * v;
            v *= 1.4142135623730951f;
            v = fminf(fmaxf(v, -256.f), 256.f);
            op[P * OH + Q] = v;
        }
    }
}

// ---------------------------------------------------------------------------
extern "C" void kernel_launch(void* const* d_in, const int* in_sizes, int n_in,
                              void* d_out, int out_size) {
    const float* x      = (const float*)d_in[0];
    const float* wl     = (const float*)d_in[1];
    const float* aw     = (const float*)d_in[2];
    const float* ab     = (const float*)d_in[3];
    const float* cw     = (const float*)d_in[4];
    const float* noise  = (const float*)d_in[5];
    const float* ns     = (const float*)d_in[6];
    const float* bias   = (const float*)d_in[7];
    float* out = (float*)d_out;

    // order chosen so gemm is launch #4 (ncu -s 5 -c 1 window lands there)
    style_kernel<<<B_, 512>>>(wl, aw, ab);
    prep_w_kernel<<<COUT, CIN>>>(cw);
    modx_t_kernel<<<dim3(CIN / 32, HW / 32, B_), dim3(32, 8)>>>(x);
    gemm_mma_kernel<<<dim3(NTOT / BN, MTOT / BM), 256>>>();
    dcoef_kernel<<<B_, COUT>>>();
    fuse_kernel<<<dim3(COUT, B_), 256>>>(noise, ns, bias, out);
}

// round 14
// speedup vs baseline: 1.5483x; 1.5483x over previous
#include <cuda_runtime.h>
#include <cuda_fp16.h>
#include <math.h>
#include <stdint.h>

// Problem constants
#define B_    16
#define CIN   512
#define COUT  512
#define HW    1024          // 32*32
#define NTOT  16384         // B_*HW
#define MTOT  4608          // 9*COUT
#define OH    64
#define OHW   4096          // 64*64

// GEMM tiling
#define BM 128
#define BN 128
#define BKE 64              // k elements per stage chunk
#define KSTEPS (CIN / BKE)  // 8
#define SROWB 144           // smem row stride bytes (16*9, ldsm conflict-free)
#define TILE_B (128 * SROWB) // 18432B per 128x64 fp16 tile
#define STAGE_B (2 * TILE_B) // A + B = 36864B

// ---- device scratch (no allocations allowed) ----
__device__ float g_style[B_ * CIN];
__device__ float g_dcoef[B_ * COUT];
__device__ float g_wsq[CIN * COUT];
__device__ __align__(256) __half g_A[(size_t)MTOT * CIN];   // [m][k] fp16
__device__ __align__(256) __half g_B[(size_t)NTOT * CIN];   // [n][k] fp16
__device__ __align__(256) float g_C[(size_t)MTOT * NTOT];   // ~302MB

// ---------------- helpers ----------------
__device__ __forceinline__ uint32_t smem_u32(const void* p) {
    uint32_t a;
    asm("{ .reg .u64 t; cvta.to.shared.u64 t, %1; cvt.u32.u64 %0, t; }" : "=r"(a) : "l"(p));
    return a;
}

#define LDSM_X4(r, addr) \
    asm volatile("ldmatrix.sync.aligned.m8n8.x4.shared.b16 {%0,%1,%2,%3}, [%4];" \
        : "=r"((r)[0]), "=r"((r)[1]), "=r"((r)[2]), "=r"((r)[3]) : "r"(addr))

#define MMA16816F16(c, a, b0v, b1v) \
    asm volatile("mma.sync.aligned.m16n8k16.row.col.f32.f16.f16.f32 " \
        "{%0,%1,%2,%3},{%4,%5,%6,%7},{%8,%9},{%0,%1,%2,%3};" \
        : "+f"((c)[0]), "+f"((c)[1]), "+f"((c)[2]), "+f"((c)[3]) \
        : "r"((a)[0]), "r"((a)[1]), "r"((a)[2]), "r"((a)[3]), "r"(b0v), "r"(b1v))

// FIR/phase mixing coefficients (see derivation in R1)
__device__ __forceinline__ float AA(int phi, int o, int ki) {
    const float tab[2][3][3] = {
        {{0.25f, 0.00f, 0.00f},
         {0.75f, 0.75f, 0.25f},
         {0.00f, 0.25f, 0.75f}},
        {{0.75f, 0.25f, 0.00f},
         {0.25f, 0.75f, 0.75f},
         {0.00f, 0.00f, 0.25f}}
    };
    return tab[phi][o][ki];
}

// ---------------------------------------------------------------------------
// 1) style[b,ci]
__global__ void style_kernel(const float* __restrict__ wl,
                             const float* __restrict__ aw,
                             const float* __restrict__ ab) {
    int b = blockIdx.x;
    __shared__ float sw[CIN];
    for (int i = threadIdx.x; i < CIN; i += blockDim.x) sw[i] = wl[b * CIN + i];
    __syncthreads();
    int warp = threadIdx.x >> 5, lane = threadIdx.x & 31;
    for (int ci = warp; ci < CIN; ci += 16) {
        float acc = 0.f;
        const float* row = aw + (size_t)ci * CIN;
        #pragma unroll 4
        for (int d = lane; d < CIN; d += 32) acc += sw[d] * row[d];
        #pragma unroll
        for (int off = 16; off; off >>= 1) acc += __shfl_xor_sync(0xffffffffu, acc, off);
        if (lane == 0)
            g_style[b * CIN + ci] = acc * 0.04419417382415922f + ab[ci];
    }
}

// ---------------------------------------------------------------------------
// 2) weights: wsq + fp16 A [m][k]
__global__ void prep_w_kernel(const float* __restrict__ cw) {
    int co = blockIdx.x;
    int ci = threadIdx.x;
    const float* wp = cw + ((size_t)co * CIN + ci) * 9;
    float w[9];
    float q = 0.f;
    #pragma unroll
    for (int t = 0; t < 9; t++) { w[t] = wp[t]; q += w[t] * w[t]; }
    g_wsq[ci * COUT + co] = q;
    #pragma unroll
    for (int t = 0; t < 9; t++)
        g_A[(size_t)(t * COUT + co) * CIN + ci] = __float2half(w[t]);
}

// ---------------------------------------------------------------------------
// 3) dcoef (launched AFTER gemm; only fuse depends on it)
__global__ void dcoef_kernel() {
    int b = blockIdx.x;
    int co = threadIdx.x;
    __shared__ float s2[CIN];
    for (int i = threadIdx.x; i < CIN; i += blockDim.x) {
        float s = g_style[b * CIN + i];
        s2[i] = s * s;
    }
    __syncthreads();
    float acc = 0.f;
    #pragma unroll 4
    for (int ci = 0; ci < CIN; ci++) acc += s2[ci] * g_wsq[ci * COUT + co];
    g_dcoef[b * COUT + co] = rsqrtf(acc + 1e-8f);
}

// ---------------------------------------------------------------------------
// 4) modulate + transpose: B[n][k] fp16
__global__ void modx_t_kernel(const float* __restrict__ x) {
    __shared__ float tile[32][33];
    int ci0 = blockIdx.x * 32, hw0 = blockIdx.y * 32, b = blockIdx.z;
    int tx = threadIdx.x, ty = threadIdx.y;
    #pragma unroll
    for (int r = 0; r < 4; r++) {
        int ci = ci0 + ty + r * 8;
        float s = g_style[b * CIN + ci];
        tile[ty + r * 8][tx] = x[((size_t)b * CIN + ci) * HW + hw0 + tx] * s;
    }
    __syncthreads();
    #pragma unroll
    for (int r = 0; r < 4; r++) {
        int hw = hw0 + ty + r * 8;
        g_B[(size_t)(b * HW + hw) * CIN + ci0 + tx] = __float2half(tile[tx][ty + r * 8]);
    }
}

// ---------------------------------------------------------------------------
// 5) GEMM via mma.sync fp16: C = A * B^T, BK=64, double-buffered
__global__ __launch_bounds__(256) void gemm_mma_kernel() {
    extern __shared__ __align__(128) char dsm[];   // 2 stages x STAGE_B

    int tid = threadIdx.x, wid = tid >> 5, lane = tid & 31;
    int m0 = blockIdx.y * BM, n0 = blockIdx.x * BN;
    int wm = wid & 1, wn = wid >> 1;   // 2 (M) x 4 (N) warps

    float acc[4][4][4];
    #pragma unroll
    for (int i = 0; i < 4; i++)
        #pragma unroll
        for (int j = 0; j < 4; j++)
            #pragma unroll
            for (int q = 0; q < 4; q++) acc[i][j][q] = 0.f;

    uint32_t sbase = smem_u32(dsm);

    auto load_stage = [&](int stg, int ks) {
        uint32_t base = sbase + stg * STAGE_B;
        int k0 = ks * BKE;
        #pragma unroll
        for (int i = 0; i < 8; i++) {
            int u = tid + 256 * i;          // 0..2047
            int t2 = u >> 10;                // 0: A, 1: B
            int v = u & 1023;
            int r = v >> 3, c = v & 7;       // 128 rows x 8 16B-chunks
            const __half* src = (t2 == 0)
                ? g_A + (size_t)(m0 + r) * CIN + k0 + c * 8
                : g_B + (size_t)(n0 + r) * CIN + k0 + c * 8;
            uint32_t dst = base + t2 * TILE_B + r * SROWB + c * 16;
            asm volatile("cp.async.cg.shared.global [%0], [%1], 16;" :: "r"(dst), "l"(src) : "memory");
        }
        asm volatile("cp.async.commit_group;" ::: "memory");
    };

    load_stage(0, 0);

    for (int s = 0; s < KSTEPS; s++) {
        asm volatile("cp.async.wait_group 0;" ::: "memory");
        __syncthreads();
        if (s + 1 < KSTEPS) load_stage((s + 1) & 1, s + 1);

        uint32_t base = sbase + (s & 1) * STAGE_B;
        uint32_t aBs = base;
        uint32_t bBs = base + TILE_B;

        #pragma unroll
        for (int kh = 0; kh < 4; kh++) {
            uint32_t koff = kh * 32 + (lane >> 4) * 16;
            uint32_t a[4][4], bfr[2][4];
            #pragma unroll
            for (int mf = 0; mf < 4; mf++) {
                int row = wm * 64 + mf * 16 + (lane & 15);
                LDSM_X4(a[mf], aBs + row * SROWB + koff);
            }
            #pragma unroll
            for (int ng = 0; ng < 2; ng++) {
                int row = wn * 32 + ng * 16 + (lane & 15);
                LDSM_X4(bfr[ng], bBs + row * SROWB + koff);
            }
            #pragma unroll
            for (int mf = 0; mf < 4; mf++)
                #pragma unroll
                for (int nf = 0; nf < 4; nf++) {
                    uint32_t b0v = bfr[nf >> 1][nf & 1];
                    uint32_t b1v = bfr[nf >> 1][(nf & 1) + 2];
                    MMA16816F16(acc[mf][nf], a[mf], b0v, b1v);
                }
        }
    }

    // epilogue: write C
    #pragma unroll
    for (int mf = 0; mf < 4; mf++) {
        int mrow = m0 + wm * 64 + mf * 16 + (lane >> 2);
        #pragma unroll
        for (int nf = 0; nf < 4; nf++) {
            int ncol = n0 + wn * 32 + nf * 8 + (lane & 3) * 2;
            *(float2*)(g_C + (size_t)mrow * NTOT + ncol) =
                make_float2(acc[mf][nf][0], acc[mf][nf][1]);
            *(float2*)(g_C + (size_t)(mrow + 8) * NTOT + ncol) =
                make_float2(acc[mf][nf][2], acc[mf][nf][3]);
        }
    }
}

// ---------------------------------------------------------------------------
// 6) fuse: FIR assembly + dcoef + noise + bias + lrelu + clamp
// Cs layout: [9][34][40], interior at rows 1..32, cols 4..35 (16B-aligned)
#define CSROW 40
__global__ __launch_bounds__(256) void fuse_kernel(const float* __restrict__ noise,
                                                   const float* __restrict__ ns_p,
                                                   const float* __restrict__ bias,
                                                   float* __restrict__ out) {
    int co = blockIdx.x, b = blockIdx.y;
    __shared__ float Cs[9][34][CSROW];   // 49 KB

    // zero-fill (vectorized)
    float4* csv = (float4*)&Cs[0][0][0];
    #pragma unroll
    for (int i = 0; i < 12; i++) {
        int idx = threadIdx.x + 256 * i;          // 0..3071, need 3060
        if (idx < 9 * 34 * CSROW / 4) csv[idx] = make_float4(0.f, 0.f, 0.f, 0.f);
    }
    __syncthreads();

    // interior load: per tap, each thread loads one float4 (aligned both sides)
    {
        int v = threadIdx.x * 4;
        int i = v >> 5, j = v & 31;
        const size_t cbase = (size_t)b * HW + i * 32 + j;
        #pragma unroll
        for (int t = 0; t < 9; t++) {
            float4 val = *(const float4*)(g_C + (size_t)(t * COUT + co) * NTOT + cbase);
            *(float4*)&Cs[t][1 + i][4 + j] = val;
        }
    }
    __syncthreads();

    int bi = threadIdx.x >> 4, bj = threadIdx.x & 15;
    float acc[4][4] = {};

    #pragma unroll
    for (int t = 0; t < 9; t++) {
        int ki = t / 3, kj = t % 3;
        float c[4][4];
        #pragma unroll
        for (int r = 0; r < 4; r++)
            #pragma unroll
            for (int cc = 0; cc < 4; cc++)
                c[r][cc] = Cs[t][2 * bi + r][3 + 2 * bj + cc];
        #pragma unroll
        for (int pi = 0; pi < 4; pi++) {
            int di = pi >> 1, phi = pi & 1;
            #pragma unroll
            for (int pj = 0; pj < 4; pj++) {
                int dj = pj >> 1, psi = pj & 1;
                #pragma unroll
                for (int oi = 0; oi < 3; oi++) {
                    float ai = AA(phi, oi, ki);
                    if (ai == 0.f) continue;
                    #pragma unroll
                    for (int oj = 0; oj < 3; oj++) {
                        float aj = AA(psi, oj, kj);
                        if (aj == 0.f) continue;
                        acc[pi][pj] += (ai * aj) * c[di + 2 - oi][dj + 2 - oj];
                    }
                }
            }
        }
    }

    float dval = g_dcoef[b * COUT + co];
    float ns = ns_p[0];
    float bv = bias[co];
    const float* np = noise + (size_t)b * OHW;
    float* op = out + ((size_t)b * COUT + co) * OHW;

    #pragma unroll
    for (int pi = 0; pi < 4; pi++) {
        int P = 4 * bi + pi;
        #pragma unroll
        for (int pj = 0; pj < 4; pj++) {
            int Q = 4 * bj + pj;
            float v = acc[pi][pj] * dval + np[P * OH + Q] * ns + bv;
            v = (v > 0.f) ? v : 0.2f * v;
            v *= 1.4142135623730951f;
            v = fminf(fmaxf(v, -256.f), 256.f);
            op[P * OH + Q] = v;
        }
    }
}

// ---------------------------------------------------------------------------
extern "C" void kernel_launch(void* const* d_in, const int* in_sizes, int n_in,
                              void* d_out, int out_size) {
    const float* x      = (const float*)d_in[0];
    const float* wl     = (const float*)d_in[1];
    const float* aw     = (const float*)d_in[2];
    const float* ab     = (const float*)d_in[3];
    const float* cw     = (const float*)d_in[4];
    const float* noise  = (const float*)d_in[5];
    const float* ns     = (const float*)d_in[6];
    const float* bias   = (const float*)d_in[7];
    float* out = (float*)d_out;

    cudaFuncSetAttribute(gemm_mma_kernel,
                         cudaFuncAttributeMaxDynamicSharedMemorySize,
                         2 * STAGE_B);

    // order chosen so gemm is launch #4 (ncu -s 5 -c 1 window lands there)
    style_kernel<<<B_, 512>>>(wl, aw, ab);
    prep_w_kernel<<<COUT, CIN>>>(cw);
    modx_t_kernel<<<dim3(CIN / 32, HW / 32, B_), dim3(32, 8)>>>(x);
    gemm_mma_kernel<<<dim3(NTOT / BN, MTOT / BM), 256, 2 * STAGE_B>>>();
    dcoef_kernel<<<B_, COUT>>>();
    fuse_kernel<<<dim3(COUT, B_), 256>>>(noise, ns, bias, out);
}

// round 15
// speedup vs baseline: 1.5623x; 1.0090x over previous
#include <cuda_runtime.h>
#include <cuda_fp16.h>
#include <math.h>
#include <stdint.h>

// Problem constants
#define B_    16
#define CIN   512
#define COUT  512
#define HW    1024          // 32*32
#define NTOT  16384         // B_*HW
#define MTOT  4608          // 9*COUT
#define OH    64
#define OHW   4096          // 64*64

// GEMM tiling: CTA 128x128x64, 4 warps (2x2), warp tile 64x64
#define BM 128
#define BN 128
#define BKE 64
#define KSTEPS (CIN / BKE)  // 8
#define SROWB 144           // smem row stride bytes (16*9, ldsm conflict-free)
#define TILE_B (128 * SROWB)
#define STAGE_B (2 * TILE_B)

// ---- device scratch (no allocations allowed) ----
__device__ float g_style[B_ * CIN];
__device__ float g_dcoef[B_ * COUT];
__device__ float g_wsq[CIN * COUT];
__device__ __align__(256) __half g_A[(size_t)MTOT * CIN];   // [m][k] fp16
__device__ __align__(256) __half g_B[(size_t)NTOT * CIN];   // [n][k] fp16
__device__ __align__(256) __half g_Ch[(size_t)MTOT * NTOT]; // C in fp16 (~151MB)

// ---------------- helpers ----------------
__device__ __forceinline__ uint32_t smem_u32(const void* p) {
    uint32_t a;
    asm("{ .reg .u64 t; cvta.to.shared.u64 t, %1; cvt.u32.u64 %0, t; }" : "=r"(a) : "l"(p));
    return a;
}

#define LDSM_X4(r, addr) \
    asm volatile("ldmatrix.sync.aligned.m8n8.x4.shared.b16 {%0,%1,%2,%3}, [%4];" \
        : "=r"((r)[0]), "=r"((r)[1]), "=r"((r)[2]), "=r"((r)[3]) : "r"(addr))

#define MMA16816F16(c, a, b0v, b1v) \
    asm volatile("mma.sync.aligned.m16n8k16.row.col.f32.f16.f16.f32 " \
        "{%0,%1,%2,%3},{%4,%5,%6,%7},{%8,%9},{%0,%1,%2,%3};" \
        : "+f"((c)[0]), "+f"((c)[1]), "+f"((c)[2]), "+f"((c)[3]) \
        : "r"((a)[0]), "r"((a)[1]), "r"((a)[2]), "r"((a)[3]), "r"(b0v), "r"(b1v))

// FIR/phase mixing coefficients (see derivation in R1)
__device__ __forceinline__ float AA(int phi, int o, int ki) {
    const float tab[2][3][3] = {
        {{0.25f, 0.00f, 0.00f},
         {0.75f, 0.75f, 0.25f},
         {0.00f, 0.25f, 0.75f}},
        {{0.75f, 0.25f, 0.00f},
         {0.25f, 0.75f, 0.75f},
         {0.00f, 0.00f, 0.25f}}
    };
    return tab[phi][o][ki];
}

// ---------------------------------------------------------------------------
// 1) style[b,ci]
__global__ void style_kernel(const float* __restrict__ wl,
                             const float* __restrict__ aw,
                             const float* __restrict__ ab) {
    int b = blockIdx.x;
    __shared__ float sw[CIN];
    for (int i = threadIdx.x; i < CIN; i += blockDim.x) sw[i] = wl[b * CIN + i];
    __syncthreads();
    int warp = threadIdx.x >> 5, lane = threadIdx.x & 31;
    for (int ci = warp; ci < CIN; ci += 16) {
        float acc = 0.f;
        const float* row = aw + (size_t)ci * CIN;
        #pragma unroll 4
        for (int d = lane; d < CIN; d += 32) acc += sw[d] * row[d];
        #pragma unroll
        for (int off = 16; off; off >>= 1) acc += __shfl_xor_sync(0xffffffffu, acc, off);
        if (lane == 0)
            g_style[b * CIN + ci] = acc * 0.04419417382415922f + ab[ci];
    }
}

// ---------------------------------------------------------------------------
// 2) weights: wsq + fp16 A [m][k]
__global__ void prep_w_kernel(const float* __restrict__ cw) {
    int co = blockIdx.x;
    int ci = threadIdx.x;
    const float* wp = cw + ((size_t)co * CIN + ci) * 9;
    float w[9];
    float q = 0.f;
    #pragma unroll
    for (int t = 0; t < 9; t++) { w[t] = wp[t]; q += w[t] * w[t]; }
    g_wsq[ci * COUT + co] = q;
    #pragma unroll
    for (int t = 0; t < 9; t++)
        g_A[(size_t)(t * COUT + co) * CIN + ci] = __float2half(w[t]);
}

// ---------------------------------------------------------------------------
// 3) dcoef (launched AFTER gemm; only fuse depends on it)
__global__ void dcoef_kernel() {
    int b = blockIdx.x;
    int co = threadIdx.x;
    __shared__ float s2[CIN];
    for (int i = threadIdx.x; i < CIN; i += blockDim.x) {
        float s = g_style[b * CIN + i];
        s2[i] = s * s;
    }
    __syncthreads();
    float acc = 0.f;
    #pragma unroll 4
    for (int ci = 0; ci < CIN; ci++) acc += s2[ci] * g_wsq[ci * COUT + co];
    g_dcoef[b * COUT + co] = rsqrtf(acc + 1e-8f);
}

// ---------------------------------------------------------------------------
// 4) modulate + transpose: B[n][k] fp16
__global__ void modx_t_kernel(const float* __restrict__ x) {
    __shared__ float tile[32][33];
    int ci0 = blockIdx.x * 32, hw0 = blockIdx.y * 32, b = blockIdx.z;
    int tx = threadIdx.x, ty = threadIdx.y;
    #pragma unroll
    for (int r = 0; r < 4; r++) {
        int ci = ci0 + ty + r * 8;
        float s = g_style[b * CIN + ci];
        tile[ty + r * 8][tx] = x[((size_t)b * CIN + ci) * HW + hw0 + tx] * s;
    }
    __syncthreads();
    #pragma unroll
    for (int r = 0; r < 4; r++) {
        int hw = hw0 + ty + r * 8;
        g_B[(size_t)(b * HW + hw) * CIN + ci0 + tx] = __float2half(tile[tx][ty + r * 8]);
    }
}

// ---------------------------------------------------------------------------
// 5) GEMM via mma.sync fp16: 4 warps, warp tile 64x64, BK=64, double-buffered
__global__ __launch_bounds__(128) void gemm_mma_kernel() {
    extern __shared__ __align__(128) char dsm[];   // 2 stages x STAGE_B

    int tid = threadIdx.x, wid = tid >> 5, lane = tid & 31;
    int m0 = blockIdx.y * BM, n0 = blockIdx.x * BN;
    int wm = wid & 1, wn = wid >> 1;   // 2 (M) x 2 (N) warps, warp tile 64x64

    float acc[4][8][4];
    #pragma unroll
    for (int i = 0; i < 4; i++)
        #pragma unroll
        for (int j = 0; j < 8; j++)
            #pragma unroll
            for (int q = 0; q < 4; q++) acc[i][j][q] = 0.f;

    uint32_t sbase = smem_u32(dsm);

    auto load_stage = [&](int stg, int ks) {
        uint32_t base = sbase + stg * STAGE_B;
        int k0 = ks * BKE;
        #pragma unroll
        for (int i = 0; i < 16; i++) {
            int u = tid + 128 * i;          // 0..2047
            int t2 = u >> 10;                // 0: A, 1: B
            int v = u & 1023;
            int r = v >> 3, c = v & 7;       // 128 rows x 8 16B-chunks
            const __half* src = (t2 == 0)
                ? g_A + (size_t)(m0 + r) * CIN + k0 + c * 8
                : g_B + (size_t)(n0 + r) * CIN + k0 + c * 8;
            uint32_t dst = base + t2 * TILE_B + r * SROWB + c * 16;
            asm volatile("cp.async.cg.shared.global [%0], [%1], 16;" :: "r"(dst), "l"(src) : "memory");
        }
        asm volatile("cp.async.commit_group;" ::: "memory");
    };

    load_stage(0, 0);

    for (int s = 0; s < KSTEPS; s++) {
        asm volatile("cp.async.wait_group 0;" ::: "memory");
        __syncthreads();
        if (s + 1 < KSTEPS) load_stage((s + 1) & 1, s + 1);

        uint32_t base = sbase + (s & 1) * STAGE_B;
        uint32_t aBs = base;
        uint32_t bBs = base + TILE_B;

        #pragma unroll
        for (int kh = 0; kh < 4; kh++) {
            uint32_t koff = kh * 32 + (lane >> 4) * 16;
            uint32_t a[4][4], bfr[4][4];
            #pragma unroll
            for (int mf = 0; mf < 4; mf++) {
                int row = wm * 64 + mf * 16 + (lane & 15);
                LDSM_X4(a[mf], aBs + row * SROWB + koff);
            }
            #pragma unroll
            for (int ng = 0; ng < 4; ng++) {
                int row = wn * 64 + ng * 16 + (lane & 15);
                LDSM_X4(bfr[ng], bBs + row * SROWB + koff);
            }
            #pragma unroll
            for (int mf = 0; mf < 4; mf++)
                #pragma unroll
                for (int nf = 0; nf < 8; nf++) {
                    uint32_t b0v = bfr[nf >> 1][nf & 1];
                    uint32_t b1v = bfr[nf >> 1][(nf & 1) + 2];
                    MMA16816F16(acc[mf][nf], a[mf], b0v, b1v);
                }
        }
    }

    // epilogue: write C as fp16
    #pragma unroll
    for (int mf = 0; mf < 4; mf++) {
        int mrow = m0 + wm * 64 + mf * 16 + (lane >> 2);
        #pragma unroll
        for (int nf = 0; nf < 8; nf++) {
            int ncol = n0 + wn * 64 + nf * 8 + (lane & 3) * 2;
            *(__half2*)(g_Ch + (size_t)mrow * NTOT + ncol) =
                __floats2half2_rn(acc[mf][nf][0], acc[mf][nf][1]);
            *(__half2*)(g_Ch + (size_t)(mrow + 8) * NTOT + ncol) =
                __floats2half2_rn(acc[mf][nf][2], acc[mf][nf][3]);
        }
    }
}

// ---------------------------------------------------------------------------
// 6) fuse: FIR assembly + dcoef + noise + bias + lrelu + clamp
// Cs layout: [9][34][40], interior at rows 1..32, cols 4..35 (16B-aligned)
#define CSROW 40
__global__ __launch_bounds__(256) void fuse_kernel(const float* __restrict__ noise,
                                                   const float* __restrict__ ns_p,
                                                   const float* __restrict__ bias,
                                                   float* __restrict__ out) {
    int co = blockIdx.x, b = blockIdx.y;
    __shared__ float Cs[9][34][CSROW];   // 49 KB

    // zero-fill (vectorized)
    float4* csv = (float4*)&Cs[0][0][0];
    #pragma unroll
    for (int i = 0; i < 12; i++) {
        int idx = threadIdx.x + 256 * i;
        if (idx < 9 * 34 * CSROW / 4) csv[idx] = make_float4(0.f, 0.f, 0.f, 0.f);
    }
    __syncthreads();

    // interior load: per tap, each thread loads 4 halfs (8B aligned both sides)
    {
        int v = threadIdx.x * 4;
        int i = v >> 5, j = v & 31;
        const size_t cbase = (size_t)b * HW + i * 32 + j;
        #pragma unroll
        for (int t = 0; t < 9; t++) {
            const __half2* cp = (const __half2*)(g_Ch + (size_t)(t * COUT + co) * NTOT + cbase);
            __half2 p0 = cp[0], p1 = cp[1];
            float2 f0 = __half22float2(p0), f1 = __half22float2(p1);
            *(float4*)&Cs[t][1 + i][4 + j] = make_float4(f0.x, f0.y, f1.x, f1.y);
        }
    }
    __syncthreads();

    int bi = threadIdx.x >> 4, bj = threadIdx.x & 15;
    float acc[4][4] = {};

    #pragma unroll
    for (int t = 0; t < 9; t++) {
        int ki = t / 3, kj = t % 3;
        float c[4][4];
        #pragma unroll
        for (int r = 0; r < 4; r++)
            #pragma unroll
            for (int cc = 0; cc < 4; cc++)
                c[r][cc] = Cs[t][2 * bi + r][3 + 2 * bj + cc];
        #pragma unroll
        for (int pi = 0; pi < 4; pi++) {
            int di = pi >> 1, phi = pi & 1;
            #pragma unroll
            for (int pj = 0; pj < 4; pj++) {
                int dj = pj >> 1, psi = pj & 1;
                #pragma unroll
                for (int oi = 0; oi < 3; oi++) {
                    float ai = AA(phi, oi, ki);
                    if (ai == 0.f) continue;
                    #pragma unroll
                    for (int oj = 0; oj < 3; oj++) {
                        float aj = AA(psi, oj, kj);
                        if (aj == 0.f) continue;
                        acc[pi][pj] += (ai * aj) * c[di + 2 - oi][dj + 2 - oj];
                    }
                }
            }
        }
    }

    float dval = g_dcoef[b * COUT + co];
    float ns = ns_p[0];
    float bv = bias[co];
    const float* np = noise + (size_t)b * OHW;
    float* op = out + ((size_t)b * COUT + co) * OHW;

    #pragma unroll
    for (int pi = 0; pi < 4; pi++) {
        int P = 4 * bi + pi;
        #pragma unroll
        for (int pj = 0; pj < 4; pj++) {
            int Q = 4 * bj + pj;
            float v = acc[pi][pj] * dval + np[P * OH + Q] * ns + bv;
            v = (v > 0.f) ? v : 0.2f * v;
            v *= 1.4142135623730951f;
            v = fminf(fmaxf(v, -256.f), 256.f);
            op[P * OH + Q] = v;
        }
    }
}

// ---------------------------------------------------------------------------
extern "C" void kernel_launch(void* const* d_in, const int* in_sizes, int n_in,
                              void* d_out, int out_size) {
    const float* x      = (const float*)d_in[0];
    const float* wl     = (const float*)d_in[1];
    const float* aw     = (const float*)d_in[2];
    const float* ab     = (const float*)d_in[3];
    const float* cw     = (const float*)d_in[4];
    const float* noise  = (const float*)d_in[5];
    const float* ns     = (const float*)d_in[6];
    const float* bias   = (const float*)d_in[7];
    float* out = (float*)d_out;

    cudaFuncSetAttribute(gemm_mma_kernel,
                         cudaFuncAttributeMaxDynamicSharedMemorySize,
                         2 * STAGE_B);

    // order chosen so gemm is launch #4 (ncu -s 5 -c 1 window lands there)
    style_kernel<<<B_, 512>>>(wl, aw, ab);
    prep_w_kernel<<<COUT, CIN>>>(cw);
    modx_t_kernel<<<dim3(CIN / 32, HW / 32, B_), dim3(32, 8)>>>(x);
    gemm_mma_kernel<<<dim3(NTOT / BN, MTOT / BM), 128, 2 * STAGE_B>>>();
    dcoef_kernel<<<B_, COUT>>>();
    fuse_kernel<<<dim3(COUT, B_), 256>>>(noise, ns, bias, out);
}